// round 3
// baseline (speedup 1.0000x reference)
#include <cuda_runtime.h>
#include <cuda_fp16.h>
#include <cstdint>

#define DINLINE __device__ __forceinline__

// ---------------- problem sizes ----------------
constexpr int M = 8192;
constexpr int N = 4096;
constexpr int K = 4096;

constexpr int BM = 128;
constexpr int BN = 128;
constexpr int BK = 64;            // 64 halfs = 128 B per smem row

constexpr int MT = M / BM;        // 64
constexpr int NT = N / BN;        // 32
constexpr int KT = K / BK;        // 64

constexpr int TILE_BYTES  = BM * BK * 2;            // 16384 (A_hi / A_lo / B each)
constexpr int STAGE_BYTES = 3 * TILE_BYTES;         // 49152
constexpr int STAGES      = 3;
constexpr int SMEM_BYTES  = STAGES * STAGE_BYTES;   // 147456
constexpr int SMEM_ALLOC  = SMEM_BYTES + 256;       // slack for 128B align

// ---------------- device scratch (no allocations allowed) ----------------
__device__ __align__(128) __half g_w [(size_t)N * K];   // 32 MB ternary fp16
__device__ __align__(128) __half g_xh[(size_t)M * K];   // 64 MB hi plane
__device__ __align__(128) __half g_xl[(size_t)M * K];   // 64 MB lo plane
__device__ float g_partial[1024];
__device__ float g_thresh;

// ---------------- PTX helpers (all legal at .target sm_103) ----------------
DINLINE uint32_t smem_u32(const void* p) {
    uint32_t a;
    asm("{ .reg .u64 t; cvta.to.shared.u64 t, %1; cvt.u32.u64 %0, t; }" : "=r"(a) : "l"(p));
    return a;
}
DINLINE void cp_async16(uint32_t dst, const void* src) {
    asm volatile("cp.async.cg.shared.global [%0], [%1], 16;" :: "r"(dst), "l"(src));
}
DINLINE void cp_commit() { asm volatile("cp.async.commit_group;" ::: "memory"); }
DINLINE void cp_wait1()  { asm volatile("cp.async.wait_group 1;" ::: "memory"); }

DINLINE void ldm4(uint32_t* r, uint32_t addr) {
    asm volatile("ldmatrix.sync.aligned.m8n8.x4.shared.b16 {%0,%1,%2,%3}, [%4];"
                 : "=r"(r[0]), "=r"(r[1]), "=r"(r[2]), "=r"(r[3]) : "r"(addr));
}
DINLINE void mma16816(float* c, const uint32_t* a, uint32_t b0, uint32_t b1) {
    asm volatile(
        "mma.sync.aligned.m16n8k16.row.col.f32.f16.f16.f32 "
        "{%0,%1,%2,%3}, {%4,%5,%6,%7}, {%8,%9}, {%0,%1,%2,%3};"
        : "+f"(c[0]), "+f"(c[1]), "+f"(c[2]), "+f"(c[3])
        : "r"(a[0]), "r"(a[1]), "r"(a[2]), "r"(a[3]), "r"(b0), "r"(b1));
}

// ---------------- preprocessing ----------------

// 1a) deterministic partial abs-sum over weight
__global__ void absmean_partial_kernel(const float* __restrict__ w) {
    __shared__ float sm[256];
    float s = 0.f;
    const size_t total = (size_t)N * K;
    for (size_t i = (size_t)blockIdx.x * 256 + threadIdx.x; i < total; i += 262144)
        s += fabsf(w[i]);
    sm[threadIdx.x] = s;
    __syncthreads();
    for (int off = 128; off > 0; off >>= 1) {
        if (threadIdx.x < off) sm[threadIdx.x] += sm[threadIdx.x + off];
        __syncthreads();
    }
    if (threadIdx.x == 0) g_partial[blockIdx.x] = sm[0];
}

// 1b) deterministic final reduction -> threshold
__global__ void absmean_final_kernel() {
    __shared__ float sm[1024];
    sm[threadIdx.x] = g_partial[threadIdx.x];
    __syncthreads();
    for (int off = 512; off > 0; off >>= 1) {
        if (threadIdx.x < off) sm[threadIdx.x] += sm[threadIdx.x + off];
        __syncthreads();
    }
    if (threadIdx.x == 0) g_thresh = 0.5f * sm[0] * (1.0f / 16777216.0f);
}

// 2) ternary quantize weight -> fp16 {-1,0,+1}, row-major [N, K]
__global__ void quantize_w_kernel(const float* __restrict__ w) {
    int idx = blockIdx.x * blockDim.x + threadIdx.x;      // 2,097,152 threads x 8 elems
    size_t base = (size_t)idx * 8;
    float t = g_thresh;
    float4 a = *reinterpret_cast<const float4*>(w + base);
    float4 b = *reinterpret_cast<const float4*>(w + base + 4);
    float v[8] = {a.x, a.y, a.z, a.w, b.x, b.y, b.z, b.w};
    union { unsigned short u[8]; uint4 q; } pk;
#pragma unroll
    for (int j = 0; j < 8; j++)
        pk.u[j] = v[j] > t ? 0x3C00u : (v[j] < -t ? 0xBC00u : 0u);  // fp16 {+1,-1,0}
    *reinterpret_cast<uint4*>(g_w + base) = pk.q;
}

// 3) split x into fp16 hi/lo planes, row-major [M, K]
__global__ void split_x_kernel(const float* __restrict__ x) {
    int idx = blockIdx.x * blockDim.x + threadIdx.x;      // 4,194,304 threads x 8 elems
    size_t base = (size_t)idx * 8;
    float4 a = *reinterpret_cast<const float4*>(x + base);
    float4 b = *reinterpret_cast<const float4*>(x + base + 4);
    float v[8] = {a.x, a.y, a.z, a.w, b.x, b.y, b.z, b.w};
    union { unsigned short u[8]; uint4 q; } hi, lo;
#pragma unroll
    for (int j = 0; j < 8; j++) {
        __half h = __float2half(v[j]);
        __half l = __float2half(v[j] - __half2float(h));
        hi.u[j] = __half_as_ushort(h);
        lo.u[j] = __half_as_ushort(l);
    }
    *reinterpret_cast<uint4*>(g_xh + base) = hi.q;
    *reinterpret_cast<uint4*>(g_xl + base) = lo.q;
}

// ---------------- GEMM: cp.async + ldmatrix + mma.sync ----------------
__global__ void __launch_bounds__(256)
gemm_kernel(const float* __restrict__ bias,
            const float* __restrict__ gamma_p,
            float* __restrict__ out) {
    extern __shared__ char smem_raw[];
    const uint32_t sb = (smem_u32(smem_raw) + 127u) & ~127u;
    const int tid = threadIdx.x;
    const int w   = tid >> 5;
    const int l   = tid & 31;
    const int n_tile = blockIdx.x;
    const int m_tile = blockIdx.y;

    // warp tile: 32m x 64n; warps laid out 4m x 2n
    const int warp_m = (w & 3) * 32;
    const int warp_n = (w >> 2) * 64;

    const __half* srcA_hi = g_xh + (size_t)(m_tile * BM) * K;
    const __half* srcA_lo = g_xl + (size_t)(m_tile * BM) * K;
    const __half* srcB    = g_w  + (size_t)(n_tile * BN) * K;

    // load one 128x64 tile triplet (A_hi, A_lo, B) into stage s for k-iter k
    auto load_stage = [&](int s, int k) {
        const uint32_t st = sb + s * STAGE_BYTES;
        const __half* srcs[3] = { srcA_hi + k * BK, srcA_lo + k * BK, srcB + k * BK };
#pragma unroll
        for (int t = 0; t < 3; t++) {
#pragma unroll
            for (int i = 0; i < 4; i++) {
                int c   = tid + i * 256;          // 1024 16B-chunks per tile
                int row = c >> 3;
                int kc  = c & 7;
                uint32_t dst = st + t * TILE_BYTES + row * 128 + ((kc ^ (row & 7)) << 4);
                cp_async16(dst, srcs[t] + (size_t)row * K + kc * 8);
            }
        }
    };

    float acc[2][8][4];
#pragma unroll
    for (int a = 0; a < 2; a++)
#pragma unroll
        for (int b = 0; b < 8; b++)
#pragma unroll
            for (int c = 0; c < 4; c++) acc[a][b][c] = 0.f;

    load_stage(0, 0); cp_commit();
    load_stage(1, 1); cp_commit();

    for (int k = 0; k < KT; k++) {
        const int s = k % 3;
        cp_wait1();
        __syncthreads();
        if (k + 2 < KT) load_stage((k + 2) % 3, k + 2);
        cp_commit();

        const uint32_t Ah = sb + s * STAGE_BYTES;
        const uint32_t Al = Ah + TILE_BYTES;
        const uint32_t Bb = Al + TILE_BYTES;

#pragma unroll
        for (int ks = 0; ks < 4; ks++) {
            const int kb = ks * 2 + (l >> 4);     // 16B chunk along k for this lane

            // B fragments: 4 x ldmatrix.x4, each covers 16n x 16k
            uint32_t bfr[4][4];
#pragma unroll
            for (int bt = 0; bt < 4; bt++) {
                int row = warp_n + bt * 16 + (l & 15);
                ldm4(bfr[bt], Bb + row * 128 + ((kb ^ (row & 7)) << 4));
            }
#pragma unroll
            for (int p = 0; p < 2; p++) {
                const uint32_t Ab = p ? Al : Ah;
                uint32_t afr[2][4];
#pragma unroll
                for (int mt = 0; mt < 2; mt++) {
                    int row = warp_m + mt * 16 + (l & 15);
                    ldm4(afr[mt], Ab + row * 128 + ((kb ^ (row & 7)) << 4));
                }
#pragma unroll
                for (int mt = 0; mt < 2; mt++)
#pragma unroll
                    for (int nt = 0; nt < 8; nt++) {
                        uint32_t b0 = (nt & 1) ? bfr[nt >> 1][1] : bfr[nt >> 1][0];
                        uint32_t b1 = (nt & 1) ? bfr[nt >> 1][3] : bfr[nt >> 1][2];
                        mma16816(acc[mt][nt], afr[mt], b0, b1);
                    }
            }
        }
    }

    // ---------------- epilogue ----------------
    const float gamma = __ldg(gamma_p);
    const int gr = m_tile * BM + warp_m + (l >> 2);
    const int gc = n_tile * BN + warp_n + (l & 3) * 2;

#pragma unroll
    for (int nt = 0; nt < 8; nt++) {
        const int col = gc + nt * 8;
        const float b0 = __ldg(bias + col);
        const float b1 = __ldg(bias + col + 1);
#pragma unroll
        for (int mt = 0; mt < 2; mt++) {
            const int r0 = gr + mt * 16;
            float2 v0, v1;
            v0.x = (acc[mt][nt][0] + b0) * gamma;
            v0.y = (acc[mt][nt][1] + b1) * gamma;
            v1.x = (acc[mt][nt][2] + b0) * gamma;
            v1.y = (acc[mt][nt][3] + b1) * gamma;
            *reinterpret_cast<float2*>(out + (size_t)r0 * N + col)       = v0;
            *reinterpret_cast<float2*>(out + (size_t)(r0 + 8) * N + col) = v1;
        }
    }
}

// ---------------- launch ----------------
extern "C" void kernel_launch(void* const* d_in, const int* in_sizes, int n_in,
                              void* d_out, int out_size) {
    const float* x     = (const float*)d_in[0];
    const float* w     = (const float*)d_in[1];
    const float* bias  = (const float*)d_in[2];
    const float* gamma = (const float*)d_in[3];
    float* out = (float*)d_out;

    absmean_partial_kernel<<<1024, 256>>>(w);
    absmean_final_kernel<<<1, 1024>>>();
    quantize_w_kernel<<<8192, 256>>>(w);
    split_x_kernel<<<16384, 256>>>(x);

    cudaFuncSetAttribute(gemm_kernel, cudaFuncAttributeMaxDynamicSharedMemorySize, SMEM_ALLOC);
    gemm_kernel<<<dim3(NT, MT), 256, SMEM_ALLOC>>>(bias, gamma, out);
}

// round 6
// speedup vs baseline: 2.0532x; 2.0532x over previous
#include <cuda_runtime.h>
#include <cuda_fp16.h>
#include <cstdint>

#define DINLINE __device__ __forceinline__

// ---------------- problem sizes ----------------
constexpr int M = 8192;
constexpr int N = 4096;
constexpr int K = 4096;

constexpr int BM = 128;
constexpr int BN = 128;
constexpr int BK = 64;            // 64 halfs = 128 B per smem row

constexpr int MT = M / BM;        // 64
constexpr int NT = N / BN;        // 32
constexpr int KT = K / BK;        // 64

constexpr int TILE_BYTES  = BM * BK * 2;            // 16384 (A / B each)
constexpr int STAGE_BYTES = 2 * TILE_BYTES;         // 32768
constexpr int STAGES      = 3;
constexpr int SMEM_BYTES  = STAGES * STAGE_BYTES;   // 98304
constexpr int SMEM_ALLOC  = SMEM_BYTES + 256;       // slack for 128B align

// ---------------- device scratch (no allocations allowed) ----------------
__device__ __align__(128) __half g_w [(size_t)N * K];   // 32 MB ternary fp16
__device__ __align__(128) __half g_xh[(size_t)M * K];   // 64 MB fp16(x)
__device__ double g_partial[1024];
__device__ float g_thresh;

// ---------------- PTX helpers (all legal at .target sm_103) ----------------
DINLINE uint32_t smem_u32(const void* p) {
    uint32_t a;
    asm("{ .reg .u64 t; cvta.to.shared.u64 t, %1; cvt.u32.u64 %0, t; }" : "=r"(a) : "l"(p));
    return a;
}
DINLINE void cp_async16(uint32_t dst, const void* src) {
    asm volatile("cp.async.cg.shared.global [%0], [%1], 16;" :: "r"(dst), "l"(src));
}
DINLINE void cp_commit() { asm volatile("cp.async.commit_group;" ::: "memory"); }
DINLINE void cp_wait1()  { asm volatile("cp.async.wait_group 1;" ::: "memory"); }

DINLINE void ldm4(uint32_t* r, uint32_t addr) {
    asm volatile("ldmatrix.sync.aligned.m8n8.x4.shared.b16 {%0,%1,%2,%3}, [%4];"
                 : "=r"(r[0]), "=r"(r[1]), "=r"(r[2]), "=r"(r[3]) : "r"(addr));
}
DINLINE void mma16816(float* c, const uint32_t* a, uint32_t b0, uint32_t b1) {
    asm volatile(
        "mma.sync.aligned.m16n8k16.row.col.f32.f16.f16.f32 "
        "{%0,%1,%2,%3}, {%4,%5,%6,%7}, {%8,%9}, {%0,%1,%2,%3};"
        : "+f"(c[0]), "+f"(c[1]), "+f"(c[2]), "+f"(c[3])
        : "r"(a[0]), "r"(a[1]), "r"(a[2]), "r"(a[3]), "r"(b0), "r"(b1));
}

// ---------------- preprocessing ----------------

// 1a) deterministic partial abs-sum over weight (double accumulation)
__global__ void absmean_partial_kernel(const float* __restrict__ w) {
    __shared__ double sm[256];
    double s = 0.0;
    const size_t total = (size_t)N * K;
    for (size_t i = (size_t)blockIdx.x * 256 + threadIdx.x; i < total; i += 262144)
        s += (double)fabsf(w[i]);
    sm[threadIdx.x] = s;
    __syncthreads();
    for (int off = 128; off > 0; off >>= 1) {
        if (threadIdx.x < off) sm[threadIdx.x] += sm[threadIdx.x + off];
        __syncthreads();
    }
    if (threadIdx.x == 0) g_partial[blockIdx.x] = sm[0];
}

// 1b) deterministic final reduction -> threshold
__global__ void absmean_final_kernel() {
    __shared__ double sm[1024];
    sm[threadIdx.x] = g_partial[threadIdx.x];
    __syncthreads();
    for (int off = 512; off > 0; off >>= 1) {
        if (threadIdx.x < off) sm[threadIdx.x] += sm[threadIdx.x + off];
        __syncthreads();
    }
    if (threadIdx.x == 0) g_thresh = (float)(0.5 * sm[0] * (1.0 / 16777216.0));
}

// 2) ternary quantize weight -> fp16 {-1,0,+1}, row-major [N, K]
__global__ void quantize_w_kernel(const float* __restrict__ w) {
    int idx = blockIdx.x * blockDim.x + threadIdx.x;      // 2,097,152 threads x 8 elems
    size_t base = (size_t)idx * 8;
    float t = g_thresh;
    float4 a = *reinterpret_cast<const float4*>(w + base);
    float4 b = *reinterpret_cast<const float4*>(w + base + 4);
    float v[8] = {a.x, a.y, a.z, a.w, b.x, b.y, b.z, b.w};
    union { unsigned short u[8]; uint4 q; } pk;
#pragma unroll
    for (int j = 0; j < 8; j++)
        pk.u[j] = v[j] > t ? 0x3C00u : (v[j] < -t ? 0xBC00u : 0u);  // fp16 {+1,-1,0}
    *reinterpret_cast<uint4*>(g_w + base) = pk.q;
}

// 3) convert x to fp16, row-major [M, K]
__global__ void convert_x_kernel(const float* __restrict__ x) {
    int idx = blockIdx.x * blockDim.x + threadIdx.x;      // 4,194,304 threads x 8 elems
    size_t base = (size_t)idx * 8;
    float4 a = *reinterpret_cast<const float4*>(x + base);
    float4 b = *reinterpret_cast<const float4*>(x + base + 4);
    float v[8] = {a.x, a.y, a.z, a.w, b.x, b.y, b.z, b.w};
    union { unsigned short u[8]; uint4 q; } hi;
#pragma unroll
    for (int j = 0; j < 8; j++)
        hi.u[j] = __half_as_ushort(__float2half(v[j]));
    *reinterpret_cast<uint4*>(g_xh + base) = hi.q;
}

// ---------------- GEMM: cp.async + ldmatrix + mma.sync ----------------
__global__ void __launch_bounds__(256, 2)
gemm_kernel(const float* __restrict__ bias,
            const float* __restrict__ gamma_p,
            float* __restrict__ out) {
    extern __shared__ char smem_raw[];
    const uint32_t sb = (smem_u32(smem_raw) + 127u) & ~127u;
    const int tid = threadIdx.x;
    const int w   = tid >> 5;
    const int l   = tid & 31;
    const int n_tile = blockIdx.x;
    const int m_tile = blockIdx.y;

    // warp tile: 32m x 64n; warps laid out 4m x 2n
    const int warp_m = (w & 3) * 32;
    const int warp_n = (w >> 2) * 64;

    const __half* srcA = g_xh + (size_t)(m_tile * BM) * K;
    const __half* srcB = g_w  + (size_t)(n_tile * BN) * K;

    // load one 128x64 tile pair (A, B) into stage s for k-iter k
    auto load_stage = [&](int s, int k) {
        const uint32_t st = sb + s * STAGE_BYTES;
        const __half* srcs[2] = { srcA + k * BK, srcB + k * BK };
#pragma unroll
        for (int t = 0; t < 2; t++) {
#pragma unroll
            for (int i = 0; i < 4; i++) {
                int c   = tid + i * 256;          // 1024 16B-chunks per tile
                int row = c >> 3;
                int kc  = c & 7;
                uint32_t dst = st + t * TILE_BYTES + row * 128 + ((kc ^ (row & 7)) << 4);
                cp_async16(dst, srcs[t] + (size_t)row * K + kc * 8);
            }
        }
    };

    float acc[2][8][4];
#pragma unroll
    for (int a = 0; a < 2; a++)
#pragma unroll
        for (int b = 0; b < 8; b++)
#pragma unroll
            for (int c = 0; c < 4; c++) acc[a][b][c] = 0.f;

    load_stage(0, 0); cp_commit();
    load_stage(1, 1); cp_commit();

    for (int k = 0; k < KT; k++) {
        const int s = k % 3;
        cp_wait1();
        __syncthreads();
        if (k + 2 < KT) load_stage((k + 2) % 3, k + 2);
        cp_commit();

        const uint32_t Ab = sb + s * STAGE_BYTES;
        const uint32_t Bb = Ab + TILE_BYTES;

#pragma unroll
        for (int ks = 0; ks < 4; ks++) {
            const int kb = ks * 2 + (l >> 4);     // 16B chunk along k for this lane

            // B fragments: 4 x ldmatrix.x4, each covers 16n x 16k
            uint32_t bfr[4][4];
#pragma unroll
            for (int bt = 0; bt < 4; bt++) {
                int row = warp_n + bt * 16 + (l & 15);
                ldm4(bfr[bt], Bb + row * 128 + ((kb ^ (row & 7)) << 4));
            }
            uint32_t afr[2][4];
#pragma unroll
            for (int mt = 0; mt < 2; mt++) {
                int row = warp_m + mt * 16 + (l & 15);
                ldm4(afr[mt], Ab + row * 128 + ((kb ^ (row & 7)) << 4));
            }
#pragma unroll
            for (int mt = 0; mt < 2; mt++)
#pragma unroll
                for (int nt = 0; nt < 8; nt++) {
                    uint32_t b0 = (nt & 1) ? bfr[nt >> 1][1] : bfr[nt >> 1][0];
                    uint32_t b1 = (nt & 1) ? bfr[nt >> 1][3] : bfr[nt >> 1][2];
                    mma16816(acc[mt][nt], afr[mt], b0, b1);
                }
        }
    }

    // ---------------- epilogue ----------------
    const float gamma = __ldg(gamma_p);
    const int gr = m_tile * BM + warp_m + (l >> 2);
    const int gc = n_tile * BN + warp_n + (l & 3) * 2;

#pragma unroll
    for (int nt = 0; nt < 8; nt++) {
        const int col = gc + nt * 8;
        const float b0 = __ldg(bias + col);
        const float b1 = __ldg(bias + col + 1);
#pragma unroll
        for (int mt = 0; mt < 2; mt++) {
            const int r0 = gr + mt * 16;
            float2 v0, v1;
            v0.x = (acc[mt][nt][0] + b0) * gamma;
            v0.y = (acc[mt][nt][1] + b1) * gamma;
            v1.x = (acc[mt][nt][2] + b0) * gamma;
            v1.y = (acc[mt][nt][3] + b1) * gamma;
            *reinterpret_cast<float2*>(out + (size_t)r0 * N + col)       = v0;
            *reinterpret_cast<float2*>(out + (size_t)(r0 + 8) * N + col) = v1;
        }
    }
}

// ---------------- launch ----------------
extern "C" void kernel_launch(void* const* d_in, const int* in_sizes, int n_in,
                              void* d_out, int out_size) {
    const float* x     = (const float*)d_in[0];
    const float* w     = (const float*)d_in[1];
    const float* bias  = (const float*)d_in[2];
    const float* gamma = (const float*)d_in[3];
    float* out = (float*)d_out;

    absmean_partial_kernel<<<1024, 256>>>(w);
    absmean_final_kernel<<<1, 1024>>>();
    quantize_w_kernel<<<8192, 256>>>(w);
    convert_x_kernel<<<16384, 256>>>(x);

    cudaFuncSetAttribute(gemm_kernel, cudaFuncAttributeMaxDynamicSharedMemorySize, SMEM_ALLOC);
    gemm_kernel<<<dim3(NT, MT), 256, SMEM_ALLOC>>>(bias, gamma, out);
}